// round 3
// baseline (speedup 1.0000x reference)
#include <cuda_runtime.h>

// Problem constants
#define B_DIM 32
#define C_DIM 8
#define HW 65536              // 256*256
#define NPAIR 64              // B * (C/4)
#define BLOCKS_PER_PAIR 32
#define NBLOCKS (NPAIR * BLOCKS_PER_PAIR)   // 2048
#define NTHREADS 256
#define F4_PER_PLANE (HW / 4)               // 16384
#define F4_PER_BLOCK (F4_PER_PLANE / BLOCKS_PER_PAIR)  // 512

// logit(0.7) = ln(7/3)
#define LOGIT_THRESH 0.8472978603872037f

// scratch: partial sums per block (msum, count, dnsum, bce) — overwritten
// every launch before being read, so no zeroing needed.
__device__ float4 g_partials[NBLOCKS];
// completion counter: zero-initialized at module load; the finisher block
// resets it to 0 each launch -> deterministic across graph replays.
__device__ unsigned int g_done_count;

__device__ __forceinline__ float4 warp_reduce4(float4 v) {
    #pragma unroll
    for (int o = 16; o > 0; o >>= 1) {
        v.x += __shfl_xor_sync(0xffffffffu, v.x, o);
        v.y += __shfl_xor_sync(0xffffffffu, v.y, o);
        v.z += __shfl_xor_sync(0xffffffffu, v.z, o);
        v.w += __shfl_xor_sync(0xffffffffu, v.w, o);
    }
    return v;
}

__device__ __forceinline__ void accum_pixel(
    float o0, float o1, float o2, float x,
    float t0, float t1, float t2, float t,
    float& msum, float& cnt, float& dnsum, float& bce)
{
    // L2 norm over the 3 image channels
    float dx = o0 - t0, dy = o1 - t1, dz = o2 - t2;
    float dn = sqrtf(fmaf(dx, dx, fmaf(dy, dy, dz * dz)));
    dnsum += dn;

    // BCE(sigmoid(x), t) with clipped logs:
    // s = log1p(exp(-|x|)); logp = -(max(-x,0)+s); log1mp = -(max(x,0)+s)
    float s = __logf(1.0f + __expf(-fabsf(x)));
    float logp  = -(fmaxf(-x, 0.0f) + s);
    float log1m = -(fmaxf( x, 0.0f) + s);
    logp  = fmaxf(logp,  -100.0f);
    log1m = fmaxf(log1m, -100.0f);
    bce += -(t * logp + (1.0f - t) * log1m);

    // mask: sigmoid(x) > 0.7  <=>  x > logit(0.7)
    float masked = (x > LOGIT_THRESH) ? dn : 0.0f;
    msum += masked;
    cnt  += (masked != 0.0f) ? 1.0f : 0.0f;
}

__global__ __launch_bounds__(NTHREADS)
void lpml_fused_kernel(const float4* __restrict__ out4,
                       const float4* __restrict__ tar4,
                       float* __restrict__ final_out)
{
    const int pair = blockIdx.x / BLOCKS_PER_PAIR;
    const int blk  = blockIdx.x % BLOCKS_PER_PAIR;
    const int b = pair >> 1;
    const int g = pair & 1;

    // base of channel 0 plane for (b, g), in float4 units
    const size_t base = (size_t)(b * C_DIM + g * 4) * F4_PER_PLANE;
    const int start = blk * F4_PER_BLOCK;

    float msum = 0.0f, cnt = 0.0f, dnsum = 0.0f, bce = 0.0f;

    #pragma unroll
    for (int it = 0; it < F4_PER_BLOCK / NTHREADS; it++) {
        const int idx = start + it * NTHREADS + threadIdx.x;
        float4 o0 = out4[base + 0 * F4_PER_PLANE + idx];
        float4 o1 = out4[base + 1 * F4_PER_PLANE + idx];
        float4 o2 = out4[base + 2 * F4_PER_PLANE + idx];
        float4 o3 = out4[base + 3 * F4_PER_PLANE + idx];
        float4 t0 = tar4[base + 0 * F4_PER_PLANE + idx];
        float4 t1 = tar4[base + 1 * F4_PER_PLANE + idx];
        float4 t2 = tar4[base + 2 * F4_PER_PLANE + idx];
        float4 t3 = tar4[base + 3 * F4_PER_PLANE + idx];

        accum_pixel(o0.x, o1.x, o2.x, o3.x, t0.x, t1.x, t2.x, t3.x, msum, cnt, dnsum, bce);
        accum_pixel(o0.y, o1.y, o2.y, o3.y, t0.y, t1.y, t2.y, t3.y, msum, cnt, dnsum, bce);
        accum_pixel(o0.z, o1.z, o2.z, o3.z, t0.z, t1.z, t2.z, t3.z, msum, cnt, dnsum, bce);
        accum_pixel(o0.w, o1.w, o2.w, o3.w, t0.w, t1.w, t2.w, t3.w, msum, cnt, dnsum, bce);
    }

    // block reduction: warp shuffle, then cross-warp via shared
    float4 v = make_float4(msum, cnt, dnsum, bce);
    v = warp_reduce4(v);

    __shared__ float4 sm[NTHREADS / 32];
    const int wid = threadIdx.x >> 5;
    const int lid = threadIdx.x & 31;
    if (lid == 0) sm[wid] = v;
    __syncthreads();

    if (wid == 0) {
        float4 w = (lid < NTHREADS / 32) ? sm[lid] : make_float4(0.f, 0.f, 0.f, 0.f);
        w = warp_reduce4(w);
        if (lid == 0) g_partials[blockIdx.x] = w;
    }

    // ---- last-block-done finalize (replaces the second kernel) ----
    __shared__ bool is_last;
    __threadfence();               // make this block's partial visible
    if (threadIdx.x == 0) {
        unsigned int prev = atomicAdd(&g_done_count, 1u);
        is_last = (prev == NBLOCKS - 1);
    }
    __syncthreads();
    if (!is_last) return;

    __threadfence();               // acquire: all partials now visible

    __shared__ float per_sample[NPAIR];
    __shared__ float bce_part[NPAIR];

    const int t = threadIdx.x;
    if (t < NPAIR) {
        float ms = 0.f, c = 0.f, dns = 0.f, bc = 0.f;
        #pragma unroll 4
        for (int i = 0; i < BLOCKS_PER_PAIR; i++) {
            float4 p = g_partials[t * BLOCKS_PER_PAIR + i];
            ms += p.x; c += p.y; dns += p.z; bc += p.w;
        }
        float fallback = dns / (float)HW;
        per_sample[t] = (c > 0.0f) ? (ms / fmaxf(c, 1.0f)) : fallback;
        bce_part[t] = bc;
    }
    __syncthreads();

    if (t == 0) {
        float nocs[2] = {0.f, 0.f};
        float bceg[2] = {0.f, 0.f};
        for (int i = 0; i < NPAIR; i++) {
            int gg = i & 1;
            nocs[gg] += per_sample[i];
            bceg[gg] += bce_part[i];
        }
        float loss = 0.0f;
        #pragma unroll
        for (int gg = 0; gg < 2; gg++) {
            float mask_loss = bceg[gg] / ((float)B_DIM * (float)HW);
            float nocs_loss = nocs[gg] / (float)B_DIM;
            loss += 0.7f * mask_loss + 0.3f * nocs_loss;
        }
        final_out[0] = loss * 0.5f;  // mean over the 2 groups
        g_done_count = 0;            // reset for next (graph-replayed) launch
    }
}

extern "C" void kernel_launch(void* const* d_in, const int* in_sizes, int n_in,
                              void* d_out, int out_size)
{
    const float4* out4 = (const float4*)d_in[0];
    const float4* tar4 = (const float4*)d_in[1];
    float* out = (float*)d_out;

    lpml_fused_kernel<<<NBLOCKS, NTHREADS>>>(out4, tar4, out);
}

// round 4
// speedup vs baseline: 1.1415x; 1.1415x over previous
#include <cuda_runtime.h>

// Problem constants
#define B_DIM 32
#define C_DIM 8
#define HW 65536              // 256*256
#define NPAIR 64              // B * (C/4)
#define BLOCKS_PER_PAIR 32
#define NBLOCKS (NPAIR * BLOCKS_PER_PAIR)   // 2048
#define NTHREADS 256
#define F4_PER_PLANE (HW / 4)               // 16384
#define F4_PER_BLOCK (F4_PER_PLANE / BLOCKS_PER_PAIR)  // 512

// logit(0.7) = ln(7/3)
#define LOGIT_THRESH 0.8472978603872037f

// scratch: partial sums per block (msum, count, dnsum, bce) — fully
// overwritten every launch before being read; no zeroing needed.
__device__ float4 g_partials[NBLOCKS];

__device__ __forceinline__ float4 warp_reduce4(float4 v) {
    #pragma unroll
    for (int o = 16; o > 0; o >>= 1) {
        v.x += __shfl_xor_sync(0xffffffffu, v.x, o);
        v.y += __shfl_xor_sync(0xffffffffu, v.y, o);
        v.z += __shfl_xor_sync(0xffffffffu, v.z, o);
        v.w += __shfl_xor_sync(0xffffffffu, v.w, o);
    }
    return v;
}

__device__ __forceinline__ void accum_pixel(
    float o0, float o1, float o2, float x,
    float t0, float t1, float t2, float t,
    float& msum, float& cnt, float& dnsum, float& bce)
{
    // L2 norm over the 3 image channels
    float dx = o0 - t0, dy = o1 - t1, dz = o2 - t2;
    float dn = sqrtf(fmaf(dx, dx, fmaf(dy, dy, dz * dz)));
    dnsum += dn;

    // BCE(sigmoid(x), t) with clipped logs:
    // s = log1p(exp(-|x|)); logp = -(max(-x,0)+s); log1mp = -(max(x,0)+s)
    float s = __logf(1.0f + __expf(-fabsf(x)));
    float logp  = -(fmaxf(-x, 0.0f) + s);
    float log1m = -(fmaxf( x, 0.0f) + s);
    logp  = fmaxf(logp,  -100.0f);
    log1m = fmaxf(log1m, -100.0f);
    bce += -(t * logp + (1.0f - t) * log1m);

    // mask: sigmoid(x) > 0.7  <=>  x > logit(0.7)
    float masked = (x > LOGIT_THRESH) ? dn : 0.0f;
    msum += masked;
    cnt  += (masked != 0.0f) ? 1.0f : 0.0f;
}

__global__ __launch_bounds__(NTHREADS)
void lpml_partial_kernel(const float4* __restrict__ out4,
                         const float4* __restrict__ tar4)
{
    const int pair = blockIdx.x / BLOCKS_PER_PAIR;
    const int blk  = blockIdx.x % BLOCKS_PER_PAIR;
    const int b = pair >> 1;
    const int g = pair & 1;

    // base of channel 0 plane for (b, g), in float4 units
    const size_t base = (size_t)(b * C_DIM + g * 4) * F4_PER_PLANE;
    const int start = blk * F4_PER_BLOCK;

    float msum = 0.0f, cnt = 0.0f, dnsum = 0.0f, bce = 0.0f;

    #pragma unroll
    for (int it = 0; it < F4_PER_BLOCK / NTHREADS; it++) {
        const int idx = start + it * NTHREADS + threadIdx.x;
        // streaming loads (no reuse -> evict-first)
        float4 o0 = __ldcs(&out4[base + 0 * F4_PER_PLANE + idx]);
        float4 o1 = __ldcs(&out4[base + 1 * F4_PER_PLANE + idx]);
        float4 o2 = __ldcs(&out4[base + 2 * F4_PER_PLANE + idx]);
        float4 o3 = __ldcs(&out4[base + 3 * F4_PER_PLANE + idx]);
        float4 t0 = __ldcs(&tar4[base + 0 * F4_PER_PLANE + idx]);
        float4 t1 = __ldcs(&tar4[base + 1 * F4_PER_PLANE + idx]);
        float4 t2 = __ldcs(&tar4[base + 2 * F4_PER_PLANE + idx]);
        float4 t3 = __ldcs(&tar4[base + 3 * F4_PER_PLANE + idx]);

        accum_pixel(o0.x, o1.x, o2.x, o3.x, t0.x, t1.x, t2.x, t3.x, msum, cnt, dnsum, bce);
        accum_pixel(o0.y, o1.y, o2.y, o3.y, t0.y, t1.y, t2.y, t3.y, msum, cnt, dnsum, bce);
        accum_pixel(o0.z, o1.z, o2.z, o3.z, t0.z, t1.z, t2.z, t3.z, msum, cnt, dnsum, bce);
        accum_pixel(o0.w, o1.w, o2.w, o3.w, t0.w, t1.w, t2.w, t3.w, msum, cnt, dnsum, bce);
    }

    // block reduction: warp shuffle, then cross-warp via shared
    float4 v = make_float4(msum, cnt, dnsum, bce);
    v = warp_reduce4(v);

    __shared__ float4 sm[NTHREADS / 32];
    const int wid = threadIdx.x >> 5;
    const int lid = threadIdx.x & 31;
    if (lid == 0) sm[wid] = v;
    __syncthreads();

    if (wid == 0) {
        float4 w = (lid < NTHREADS / 32) ? sm[lid] : make_float4(0.f, 0.f, 0.f, 0.f);
        w = warp_reduce4(w);
        if (lid == 0) g_partials[blockIdx.x] = w;
    }
}

// Finalize: 256 threads. 4 threads per pair, each sums 8 of the 32 partials
// (all 2048 L2-hot loads in flight at once), shfl-combine across the 4 lanes,
// then a flat weighted reduction of the 64 per-pair contributions.
__global__ __launch_bounds__(256)
void lpml_finalize_kernel(float* __restrict__ out)
{
    const int t    = threadIdx.x;
    const int pair = t >> 2;        // 0..63
    const int sub  = t & 3;         // 0..3

    float ms = 0.f, c = 0.f, dns = 0.f, bc = 0.f;
    #pragma unroll
    for (int i = 0; i < 8; i++) {
        float4 p = g_partials[pair * BLOCKS_PER_PAIR + sub * 8 + i];
        ms += p.x; c += p.y; dns += p.z; bc += p.w;
    }
    // combine the 4 sub-lanes (lanes pair*4 .. pair*4+3 are in the same warp)
    #pragma unroll
    for (int o = 1; o <= 2; o <<= 1) {
        ms  += __shfl_xor_sync(0xffffffffu, ms,  o);
        c   += __shfl_xor_sync(0xffffffffu, c,   o);
        dns += __shfl_xor_sync(0xffffffffu, dns, o);
        bc  += __shfl_xor_sync(0xffffffffu, bc,  o);
    }

    __shared__ float contrib[NPAIR];
    if (sub == 0) {
        float fallback   = dns * (1.0f / (float)HW);
        float per_sample = (c > 0.0f) ? (ms / fmaxf(c, 1.0f)) : fallback;
        // final loss = (1/2) * sum over 64 pairs of
        //   [0.7*bce/(B*HW) + 0.3*per_sample/B]
        contrib[pair] = 0.7f * bc * (1.0f / ((float)B_DIM * (float)HW))
                      + 0.3f * per_sample * (1.0f / (float)B_DIM);
    }
    __syncthreads();

    if (t < 32) {
        float v = contrib[t] + contrib[t + 32];
        #pragma unroll
        for (int o = 16; o > 0; o >>= 1)
            v += __shfl_xor_sync(0xffffffffu, v, o);
        if (t == 0) out[0] = v * 0.5f;
    }
}

extern "C" void kernel_launch(void* const* d_in, const int* in_sizes, int n_in,
                              void* d_out, int out_size)
{
    const float4* out4 = (const float4*)d_in[0];
    const float4* tar4 = (const float4*)d_in[1];
    float* out = (float*)d_out;

    lpml_partial_kernel<<<NBLOCKS, NTHREADS>>>(out4, tar4);
    lpml_finalize_kernel<<<1, 256>>>(out);
}